// round 2
// baseline (speedup 1.0000x reference)
#include <cuda_runtime.h>
#include <math.h>

#define NBOX 8192
#define LCLS 8
#define CAP  1536          // max boxes per label (17 sigma above binomial mean 1024)
#define NT   256
#define NW   (NT / 32)
#define MAXK 6             // ceil(CAP / NT)

// Scratch (no allocations allowed): per-label keep lists + counts.
__device__ int d_keep[LCLS * CAP];
__device__ int d_kc[LCLS];

__global__ __launch_bounds__(NT, 1)
void softnms_kernel(const float4* __restrict__ boxes,
                    const float* __restrict__ scores,
                    const int* __restrict__ labels)
{
    const int l    = blockIdx.x;
    const int t    = threadIdx.x;
    const int warp = t >> 5;
    const int lane = t & 31;

    __shared__ float4   sBox[CAP];
    __shared__ float    sScore[CAP];
    __shared__ int      sOrder[CAP];
    __shared__ int      sWCnt[NW];
    __shared__ unsigned sRKey[NW], sRP[NW], sRPC[NW];
    __shared__ int      sBase;
    __shared__ unsigned sSelP;

    // ---------------- stable per-label compaction ----------------
    if (t == 0) sBase = 0;
    __syncthreads();

    for (int start = 0; start < NBOX; start += NT) {
        const int j = start + t;
        const bool flag = (labels[j] == l);
        const unsigned ball = __ballot_sync(0xffffffffu, flag);
        const int wpre = __popc(ball & ((1u << lane) - 1u));
        if (lane == 0) sWCnt[warp] = __popc(ball);
        __syncthreads();
        int pre = 0, tot = 0;
#pragma unroll
        for (int w = 0; w < NW; w++) {
            const int c = sWCnt[w];
            if (w < warp) pre += c;
            tot += c;
        }
        if (flag) {
            const int p = sBase + pre + wpre;
            if (p < CAP) {
                sOrder[p] = j;
                sScore[p] = scores[j];
                sBox[p]   = boxes[j];
            }
        }
        __syncthreads();
        if (t == 0) sBase += tot;
        __syncthreads();
    }

    const int m     = min(sBase, CAP);
    const int K     = (m + NT - 1) / NT;   // contiguous elements per thread
    const int pBase = t * K;

    // Per-thread register-resident working set
    float ws[MAXK], ax[MAXK], ay[MAXK], bx[MAXK], by[MAXK], area[MAXK];
#pragma unroll
    for (int k = 0; k < MAXK; k++) {
        const int p = pBase + k;
        const bool v = (k < K) && (p < m);
        ws[k] = v ? sScore[p] : -1.0f;
        const float4 b = v ? sBox[p] : make_float4(0.f, 0.f, 0.f, 0.f);
        ax[k] = b.x; ay[k] = b.y; bx[k] = b.z; by[k] = b.w;
        area[k] = (b.z - b.x) * (b.w - b.y);
    }

    // ---------------- sequential Soft-NMS loop ----------------
    int kc = 0;
    for (;;) {
        // local ordered argmax over my K contiguous elements
        // carried: (key = score bits, pp = element index, pos = alive rank, cnt = alive count)
        unsigned key = 0u, pp = 0u, pos = 0u, cnt = 0u;
#pragma unroll
        for (int k = 0; k < MAXK; k++) {
            if (k >= K) break;
            const bool alive = ws[k] >= 0.0f;
            const unsigned ek = alive ? __float_as_uint(ws[k]) : 0u;  // scores > 0 while alive
            if (ek > key) { key = ek; pp = (unsigned)(pBase + k); pos = cnt; }
            cnt += alive ? 1u : 0u;
        }
        // warp-level ordered reduce: power-of-two shfl_down keeps segments contiguous,
        // tie keeps left => lowest index (matches jnp.argmax first-max)
#pragma unroll
        for (int off = 1; off < 32; off <<= 1) {
            const unsigned rkey = __shfl_down_sync(0xffffffffu, key, off);
            const unsigned rpp  = __shfl_down_sync(0xffffffffu, pp, off);
            const unsigned rpc  = __shfl_down_sync(0xffffffffu, (pos << 16) | cnt, off);
            const unsigned rpos = rpc >> 16, rcnt = rpc & 0xffffu;
            if (rkey > key) { key = rkey; pp = rpp; pos = cnt + rpos; }
            cnt += rcnt;
        }
        if (lane == 0) {
            sRKey[warp] = key; sRP[warp] = pp; sRPC[warp] = (pos << 16) | cnt;
        }
        __syncthreads();
        if (warp == 0) {
            unsigned k2 = 0u, p2 = 0u, po2 = 0u, c2 = 0u;
            if (lane < NW) {
                k2 = sRKey[lane]; p2 = sRP[lane];
                const unsigned pc = sRPC[lane];
                po2 = pc >> 16; c2 = pc & 0xffffu;
            }
#pragma unroll
            for (int off = 1; off < NW; off <<= 1) {
                const unsigned rkey = __shfl_down_sync(0xffffffffu, k2, off);
                const unsigned rpp  = __shfl_down_sync(0xffffffffu, p2, off);
                const unsigned rpc  = __shfl_down_sync(0xffffffffu, (po2 << 16) | c2, off);
                const unsigned rpos = rpc >> 16, rcnt = rpc & 0xffffu;
                if (rkey > k2) { k2 = rkey; p2 = rpp; po2 = c2 + rpos; }
                c2 += rcnt;
            }
            if (lane == 0) {
                if (c2 == 0u) {
                    sSelP = 0xffffffffu;                    // no alive boxes -> done
                } else {
                    sSelP = p2;
                    d_keep[l * CAP + kc] = sOrder[po2];     // order[pos]  (reference bug, faithfully)
                }
            }
        }
        __syncthreads();
        const unsigned selP = sSelP;
        if (selP == 0xffffffffu) break;
        kc++;

        // decay everyone still alive vs. the selected box, then re-apply SCORE_THR to ALL
        // alive boxes (reference: alive = others & (cs >= SCORE_THR) every iteration)
        const float4 sb = sBox[selP];                       // broadcast LDS
        const float aS = (sb.z - sb.x) * (sb.w - sb.y);
#pragma unroll
        for (int k = 0; k < MAXK; k++) {
            if (k >= K) break;
            if (ws[k] < 0.0f) continue;
            if ((unsigned)(pBase + k) == selP) { ws[k] = -1.0f; continue; }
            float nv = ws[k];
            const float lx = fmaxf(sb.x, ax[k]);
            const float ly = fmaxf(sb.y, ay[k]);
            const float rx = fminf(sb.z, bx[k]);
            const float ry = fminf(sb.w, by[k]);
            const float w = rx - lx, h = ry - ly;
            if (w > 0.0f && h > 0.0f) {                     // else iou=0 -> decay=exp(-0)=1 exactly
                const float inter = w * h;
                const float iou = inter / (aS + area[k] - inter + 1e-8f);
                const float arg = -(iou * iou) * 2.0f;      // f32-rounded arg, exactly as jax
                const float dec = (float)exp((double)arg);  // correctly-rounded f32 exp
                nv = nv * dec;
            }
            ws[k] = (nv >= 0.001f) ? nv : -1.0f;            // SCORE_THR applies to all alive
        }
    }

    if (t == 0) d_kc[l] = kc;
}

// ---------------- gather + pack outputs ----------------
// Layout (float32): boxes[N*4] | scores[N] | labels[N] | count[1]
__global__ void gather_kernel(const float4* __restrict__ boxes,
                              const float* __restrict__ scores,
                              const int* __restrict__ labels,
                              float* __restrict__ out)
{
    const int j = blockIdx.x * blockDim.x + threadIdx.x;

    int off[LCLS + 1];
    off[0] = 0;
#pragma unroll
    for (int l = 0; l < LCLS; l++) off[l + 1] = off[l] + d_kc[l];
    const int total = off[LCLS];

    if (j == 0) out[NBOX * 6] = (float)total;
    if (j >= NBOX) return;

    float4 b = make_float4(0.f, 0.f, 0.f, 0.f);
    float s = 0.f, lab = 0.f;
    if (j < total) {
        int l = 0;
#pragma unroll
        for (int q = 1; q < LCLS; q++) if (j >= off[q]) l = q;
        const int g = d_keep[l * CAP + (j - off[l])];
        b = boxes[g];
        s = scores[g];
        lab = (float)labels[g];
    }
    reinterpret_cast<float4*>(out)[j] = b;
    out[NBOX * 4 + j] = s;
    out[NBOX * 5 + j] = lab;
}

extern "C" void kernel_launch(void* const* d_in, const int* in_sizes, int n_in,
                              void* d_out, int out_size)
{
    const float4* boxes  = (const float4*)d_in[0];
    const float*  scores = (const float*)d_in[1];
    const int*    labels = (const int*)d_in[2];
    float* out = (float*)d_out;

    softnms_kernel<<<LCLS, NT>>>(boxes, scores, labels);
    gather_kernel<<<NBOX / NT, NT>>>(boxes, scores, labels, out);
}

// round 3
// speedup vs baseline: 1.1893x; 1.1893x over previous
#include <cuda_runtime.h>
#include <math.h>

#define NBOX 8192
#define LCLS 8
#define CAP  1536          // max boxes per label
#define NT   256
#define NW   (NT / 32)
#define MAXK 6
#define FULLMASK 0xffffffffu

// Scratch (no allocations allowed): per-label keep lists + counts.
__device__ int d_keep[LCLS * CAP];
__device__ int d_kc[LCLS];

// ---------------------------------------------------------------------------
// float-float exp(x) for x in (-2, 0], FFMA-only hot path.
// e^x = 2^e * T[k] * (1 + r + r^2*(1/2 + r/6 + r^2/24)),  n = rint(x*512/ln2),
// e = n>>9, k = n&511, r = x - n*ln2/512 held as (rh, rl) float-float.
// Total relative error ~2^-44 -> result equals correctly-rounded f32 exp
// except with probability ~2^-20 per call (1-ulp).
// ---------------------------------------------------------------------------
__device__ __forceinline__ float exp_ff(float x, const float2* __restrict__ tab,
                                        float L2c, float L3c)
{
    const float I   = 738.66585811433f;   // 512/ln2
    const float L1c = 0x1.62ep-10f;       // 13-bit head of ln2/512 (n*L1 exact)

    float nf = rintf(x * I);
    int   n  = (int)nf;
    float a  = fmaf(-nf, L1c, x);         // exact (Sterbenz cancellation)
    float t  = nf * L2c;
    // 2Sum(a, -t)
    float b   = -t;
    float rh  = a + b;
    float bb  = rh - a;
    float err = (a - (rh - bb)) + (b - bb);
    float dt  = fmaf(nf, L2c, -t);        // exact rounding residual of t
    float rl  = err - dt - nf * L3c;
    // poly: q = 1/2 + r/6 + r^2/24 ; s = r^2*q
    float q = fmaf(rh, 0.041666668f, 0.16666667f);
    q       = fmaf(rh, q, 0.5f);
    float s = (rh * rh) * q;
    // mantissa m = 1 + rh + (rl + ul + s) as float-float
    float uh  = 1.0f + rh;
    float ul  = rh - (uh - 1.0f);
    float low = (ul + rl) + s;
    float mh  = uh + low;
    float ml  = low - (mh - uh);
    // multiply by table entry (Th, Tl)
    int e = n >> 9;
    int k = n - (e << 9);
    float2 T = tab[k];
    float ph = T.x * mh;
    float pl = fmaf(T.x, mh, -ph);        // exact
    pl = fmaf(T.x, ml, pl);
    pl = fmaf(T.y, mh, pl);
    float se = __int_as_float((127 + e) << 23);   // 2^e, e in [-3,0]
    return fmaf(ph, se, pl * se);
}

__global__ __launch_bounds__(NT, 1)
void softnms_kernel(const float4* __restrict__ boxes,
                    const float* __restrict__ scores,
                    const int* __restrict__ labels)
{
    const int l    = blockIdx.x;
    const int t    = threadIdx.x;
    const int warp = t >> 5;
    const int lane = t & 31;

    __shared__ float4   sBox[CAP];
    __shared__ float    sScore[CAP];
    __shared__ int      sOrder[CAP];
    __shared__ float2   sTab[512];
    __shared__ float    sL2c, sL3c;
    __shared__ int      sWCnt[NW];
    __shared__ unsigned bKey[2][NW], bPP[2][NW];
    __shared__ int      bRank[2][NW], bCnt[2][NW];
    __shared__ int      sBase;

    // ---------------- one-time prologue: exp table + reduction constants ----
    for (int q = t; q < 512; q += NT) {
        double v = exp2((double)q * (1.0 / 512.0));
        float hi = (float)v;
        sTab[q] = make_float2(hi, (float)(v - (double)hi));
    }
    if (t == 0) {
        double Ld = 0.69314718055994530941723212145818 / 512.0;
        const float L1c = 0x1.62ep-10f;
        float l2 = (float)(Ld - (double)L1c);
        sL2c = l2;
        sL3c = (float)(Ld - (double)L1c - (double)l2);
        sBase = 0;
    }
    __syncthreads();

    // ---------------- stable per-label compaction ----------------
    for (int start = 0; start < NBOX; start += NT) {
        const int j = start + t;
        const bool flag = (labels[j] == l);
        const unsigned ball = __ballot_sync(FULLMASK, flag);
        const int wpre = __popc(ball & ((1u << lane) - 1u));
        if (lane == 0) sWCnt[warp] = __popc(ball);
        __syncthreads();
        int pre = 0, tot = 0;
#pragma unroll
        for (int w = 0; w < NW; w++) {
            const int c = sWCnt[w];
            if (w < warp) pre += c;
            tot += c;
        }
        if (flag) {
            const int p = sBase + pre + wpre;
            if (p < CAP) {
                sOrder[p] = j;
                sScore[p] = scores[j];
                sBox[p]   = boxes[j];
            }
        }
        __syncthreads();
        if (t == 0) sBase += tot;
        __syncthreads();
    }

    const int m     = min(sBase, CAP);
    const int K     = (m + NT - 1) / NT;   // contiguous elements per thread
    const int pBase = t * K;
    const float L2c = sL2c, L3c = sL3c;

    // Per-thread register-resident working set
    float ws[MAXK], ax[MAXK], ay[MAXK], bx[MAXK], by[MAXK], area[MAXK];
#pragma unroll
    for (int k = 0; k < MAXK; k++) {
        const int p = pBase + k;
        const bool v = (k < K) && (p < m);
        ws[k] = v ? sScore[p] : -1.0f;
        const float4 bb = v ? sBox[p] : make_float4(0.f, 0.f, 0.f, 0.f);
        ax[k] = bb.x; ay[k] = bb.y; bx[k] = bb.z; by[k] = bb.w;
        area[k] = (bb.z - bb.x) * (bb.w - bb.y);
    }

    // ---------------- sequential Soft-NMS loop ----------------
    int kc = 0;
    int par = 0;
    for (;;) {
        // local ordered argmax over my K contiguous elements
        unsigned key = 0u, pp = 0u, pos = 0u;
        int cnt = 0;
#pragma unroll
        for (int k = 0; k < MAXK; k++) {
            if (k >= K) break;
            const bool alive = ws[k] >= 0.0f;
            const unsigned ek = alive ? __float_as_uint(ws[k]) : 0u;
            if (ek > key) { key = ek; pp = (unsigned)(pBase + k); pos = (unsigned)cnt; }
            cnt += alive ? 1 : 0;
        }
        // warp argmax via redux: first-max = lowest lane among key==max
        const unsigned wmax = __reduce_max_sync(FULLMASK, key);
        const unsigned ball = __ballot_sync(FULLMASK, key == wmax);
        const int wl = __ffs(ball) - 1;
        const int below = __reduce_add_sync(FULLMASK, (lane < wl) ? cnt : 0);
        const int wcnt  = __reduce_add_sync(FULLMASK, cnt);
        const unsigned wpp  = __shfl_sync(FULLMASK, pp, wl);
        const unsigned wpos = __shfl_sync(FULLMASK, pos, wl);
        if (lane == 0) {
            bKey[par][warp]  = wmax;
            bPP[par][warp]   = wpp;
            bRank[par][warp] = below + (int)wpos;
            bCnt[par][warp]  = wcnt;
        }
        __syncthreads();
        // redundant block-level reduce (warp order => first-max)
        unsigned bk = 0u, bpp = 0u;
        int brank = 0, acc = 0;
#pragma unroll
        for (int w = 0; w < NW; w++) {
            const unsigned kw = bKey[par][w];
            if (kw > bk) { bk = kw; bpp = bPP[par][w]; brank = acc + bRank[par][w]; }
            acc += bCnt[par][w];
        }
        if (acc == 0) break;
        if (t == 0) d_keep[l * CAP + kc] = sOrder[brank];
        kc++;
        par ^= 1;
        const int selP = (int)bpp;

        // decay everyone still alive vs. the selected box; re-apply SCORE_THR
        const float4 sb = sBox[selP];
        const float aS = (sb.z - sb.x) * (sb.w - sb.y);
#pragma unroll
        for (int k = 0; k < MAXK; k++) {
            if (k >= K) break;
            if (ws[k] < 0.0f) continue;
            if (pBase + k == selP) { ws[k] = -1.0f; continue; }
            float nv = ws[k];
            const float lx = fmaxf(sb.x, ax[k]);
            const float ly = fmaxf(sb.y, ay[k]);
            const float rx = fminf(sb.z, bx[k]);
            const float ry = fminf(sb.w, by[k]);
            const float w = rx - lx, h = ry - ly;
            if (w > 0.0f && h > 0.0f) {            // else decay = exp(-0) = 1 exactly
                const float inter = w * h;
                const float iou = inter / (aS + area[k] - inter + 1e-8f);
                const float arg = -(iou * iou) * 2.0f;
                const float dec = exp_ff(arg, sTab, L2c, L3c);
                nv = nv * dec;
            }
            ws[k] = (nv >= 0.001f) ? nv : -1.0f;   // SCORE_THR applies to all alive
        }
    }

    if (t == 0) d_kc[l] = kc;
}

// ---------------- gather + pack outputs ----------------
// Layout (float32): boxes[N*4] | scores[N] | labels[N] | count[1]
__global__ void gather_kernel(const float4* __restrict__ boxes,
                              const float* __restrict__ scores,
                              const int* __restrict__ labels,
                              float* __restrict__ out)
{
    const int j = blockIdx.x * blockDim.x + threadIdx.x;

    int off[LCLS + 1];
    off[0] = 0;
#pragma unroll
    for (int l = 0; l < LCLS; l++) off[l + 1] = off[l] + d_kc[l];
    const int total = off[LCLS];

    if (j == 0) out[NBOX * 6] = (float)total;
    if (j >= NBOX) return;

    float4 b = make_float4(0.f, 0.f, 0.f, 0.f);
    float s = 0.f, lab = 0.f;
    if (j < total) {
        int l = 0;
#pragma unroll
        for (int q = 1; q < LCLS; q++) if (j >= off[q]) l = q;
        const int g = d_keep[l * CAP + (j - off[l])];
        b = boxes[g];
        s = scores[g];
        lab = (float)labels[g];
    }
    reinterpret_cast<float4*>(out)[j] = b;
    out[NBOX * 4 + j] = s;
    out[NBOX * 5 + j] = lab;
}

extern "C" void kernel_launch(void* const* d_in, const int* in_sizes, int n_in,
                              void* d_out, int out_size)
{
    const float4* boxes  = (const float4*)d_in[0];
    const float*  scores = (const float*)d_in[1];
    const int*    labels = (const int*)d_in[2];
    float* out = (float*)d_out;

    softnms_kernel<<<LCLS, NT>>>(boxes, scores, labels);
    gather_kernel<<<NBOX / NT, NT>>>(boxes, scores, labels, out);
}